// round 6
// baseline (speedup 1.0000x reference)
#include <cuda_runtime.h>
#include <cstdint>

// out[b,i,j] = x[b, i, i+j] if i+j < L else 0
// B=4, L=4096, LIMIT=256
#define MAXLEN 4096
#define LIMIT  256
#define BATCH  4

#define NROWS     (BATCH * MAXLEN)   // 16384
#define RPC       32                 // rows per CTA
#define TPB       128                // 4 warps; each warp consumes 8 rows
#define NBLOCKS   (NROWS / RPC)      // 512
#define SLOT_B    1056               // bytes per smem row slot (65 f4 data + pad)

__device__ __forceinline__ uint32_t smem_u32(const void* p) {
    uint32_t a;
    asm("{ .reg .u64 t; cvta.to.shared.u64 t, %1; cvt.u32.u64 %0, t; }"
        : "=r"(a) : "l"(p));
    return a;
}

__global__ __launch_bounds__(TPB)
void band_gather_kernel(const float* __restrict__ x, float* __restrict__ out)
{
    __shared__ __align__(16) unsigned char buf[RPC * SLOT_B];
    __shared__ __align__(8) uint64_t mbar;

    const int tid  = threadIdx.x;
    const int lane = tid & 31;
    const int wrp  = tid >> 5;

    const uint32_t mbar_a = smem_u32(&mbar);

    if (tid == 0) {
        asm volatile("mbarrier.init.shared.b64 [%0], %1;"
                     :: "r"(mbar_a), "r"(RPC) : "memory");
    }
    __syncthreads();

    // ---- Phase 1: 32 threads each issue one bulk read of their row window ----
    if (tid < RPC) {
        const int row = blockIdx.x * RPC + tid;    // b*L + i
        const int i   = row & (MAXLEN - 1);
        const int a0  = i & ~3;                    // 16B-aligned start col
        const uint32_t bytes =
            min((uint32_t)1040u, (uint32_t)((MAXLEN - a0) * 4));
        const float* src = x + ((size_t)row << 12) + a0;
        const uint32_t dst = smem_u32(buf) + tid * SLOT_B;

        asm volatile("mbarrier.arrive.expect_tx.shared.b64 _, [%0], %1;"
                     :: "r"(mbar_a), "r"(bytes) : "memory");
        // Canonical Hopper-era bulk-copy form (shared::cluster dst qualifier).
        asm volatile(
            "cp.async.bulk.shared::cluster.global.mbarrier::complete_tx::bytes "
            "[%0], [%1], %2, [%3];"
            :: "r"(dst), "l"(src), "r"(bytes), "r"(mbar_a) : "memory");
    }

    // ---- Wait for all 32 row windows (phase 0) ----
    {
        uint32_t done;
        asm volatile(
            "{\n\t.reg .pred p;\n\t"
            "mbarrier.try_wait.parity.acquire.cta.shared::cta.b64 p, [%1], 0;\n\t"
            "selp.b32 %0, 1, 0, p;\n\t}"
            : "=r"(done) : "r"(mbar_a) : "memory");
        if (!done) {
            asm volatile(
                "{\n\t.reg .pred P1;\n\t"
                "WL_%=:\n\t"
                "mbarrier.try_wait.parity.acquire.cta.shared::cta.b64 P1, [%0], 0, 0x989680;\n\t"
                "@P1 bra.uni WD_%=;\n\t"
                "bra.uni WL_%=;\n\t"
                "WD_%=:\n\t}"
                :: "r"(mbar_a) : "memory");
        }
    }

    // ---- Phase 2: funnel-shift out of smem, coalesced STG.128 ----
    #pragma unroll
    for (int rr = 0; rr < RPC / 4; rr++) {          // 8 rows per warp
        const int r_loc = wrp * (RPC / 4) + rr;
        const int row   = blockIdx.x * RPC + r_loc;
        const int i     = row & (MAXLEN - 1);
        const int a     = i & 3;                    // shift (warp-uniform)
        const int lim   = MAXLEN - i;               // j < lim valid

        const float4* sl =
            reinterpret_cast<const float4*>(buf + r_loc * SLOT_B);
        float4* orow = reinterpret_cast<float4*>(out) + ((size_t)row << 6);

        #pragma unroll
        for (int it = 0; it < 2; it++) {
            const int o  = lane + it * 32;          // output f4 index 0..63
            const float4 w0 = sl[o];
            const float4 w1 = sl[o + 1];

            float4 v;
            if      (a == 0) { v.x = w0.x; v.y = w0.y; v.z = w0.z; v.w = w0.w; }
            else if (a == 1) { v.x = w0.y; v.y = w0.z; v.z = w0.w; v.w = w1.x; }
            else if (a == 2) { v.x = w0.z; v.y = w0.w; v.z = w1.x; v.w = w1.y; }
            else             { v.x = w0.w; v.y = w1.x; v.z = w1.y; v.w = w1.z; }

            const int j0 = o << 2;
            if (j0 + 3 >= lim) {                    // tail rows only
                if (j0 + 0 >= lim) v.x = 0.0f;
                if (j0 + 1 >= lim) v.y = 0.0f;
                if (j0 + 2 >= lim) v.z = 0.0f;
                if (j0 + 3 >= lim) v.w = 0.0f;
            }
            orow[o] = v;
        }
    }
}

extern "C" void kernel_launch(void* const* d_in, const int* in_sizes, int n_in,
                              void* d_out, int out_size)
{
    (void)in_sizes; (void)n_in; (void)out_size;
    const float* x = (const float*)d_in[0];
    float* out = (float*)d_out;
    band_gather_kernel<<<NBLOCKS, TPB>>>(x, out);
}

// round 7
// speedup vs baseline: 1.0786x; 1.0786x over previous
#include <cuda_runtime.h>
#include <cstdint>

// out[b,i,j] = x[b, i, i+j] if i+j < L else 0
// B=4, L=4096, LIMIT=256
#define MAXLEN 4096
#define LIMIT  256
#define BATCH  4

#define NROWS     (BATCH * MAXLEN)    // 16384
#define NSM       148
#define OCC       8
#define NBLOCKS   (NSM * OCC)         // 1184 persistent CTAs (one wave)
#define TPB       256                 // 8 warps; warp handles one row per trip
#define ROWSTRIDE (NBLOCKS * (TPB/32))// 9472 rows per sweep

__device__ __forceinline__ void do_row(const float* __restrict__ x,
                                       float* __restrict__ out,
                                       int row, int lane)
{
    const int i   = row & (MAXLEN - 1);
    const int a   = i & 3;                   // misalignment, warp-uniform
    const int bc4 = i >> 2;                  // first aligned f4 block in row
    const int lim = MAXLEN - i;              // j < lim is valid
    const float4* __restrict__ xr =
        reinterpret_cast<const float4*>(x) + ((size_t)row << 10);
    float4* __restrict__ orow =
        reinterpret_cast<float4*>(out) + ((size_t)row << 6);

    // 4 front-batched LDG.128 covering the 65-f4 source window
    const int q0a = min(bc4 + lane,      1023);
    const int q1a = min(bc4 + lane + 1,  1023);
    const int q0b = min(bc4 + lane + 32, 1023);
    const int q1b = min(bc4 + lane + 33, 1023);
    float4 w0a = __ldg(xr + q0a);
    float4 w1a = __ldg(xr + q1a);
    float4 w0b = __ldg(xr + q0b);
    float4 w1b = __ldg(xr + q1b);

    #pragma unroll
    for (int it = 0; it < 2; it++) {
        const int o = lane + it * 32;        // output f4 index (0..63)
        float4 w0 = it ? w0b : w0a;
        float4 w1 = it ? w1b : w1a;

        float4 v;                            // funnel shift by a floats
        if      (a == 0) { v.x = w0.x; v.y = w0.y; v.z = w0.z; v.w = w0.w; }
        else if (a == 1) { v.x = w0.y; v.y = w0.z; v.z = w0.w; v.w = w1.x; }
        else if (a == 2) { v.x = w0.z; v.y = w0.w; v.z = w1.x; v.w = w1.y; }
        else             { v.x = w0.w; v.y = w1.x; v.z = w1.y; v.w = w1.z; }

        const int j0 = o << 2;
        if (j0 + 3 >= lim) {                 // rare tail rows only
            if (j0 + 0 >= lim) v.x = 0.0f;
            if (j0 + 1 >= lim) v.y = 0.0f;
            if (j0 + 2 >= lim) v.z = 0.0f;
            if (j0 + 3 >= lim) v.w = 0.0f;
        }
        orow[o] = v;
    }
}

__global__ __launch_bounds__(TPB, OCC)
void band_gather_kernel(const float* __restrict__ x, float* __restrict__ out)
{
    const int lane = threadIdx.x & 31;
    const int warp = blockIdx.x * (TPB / 32) + (threadIdx.x >> 5);

    // Trip 1: always valid (warp < 9472 < 16384)
    do_row(x, out, warp, lane);

    // Trip 2: predicated (covers rows 9472..16383)
    const int row2 = warp + ROWSTRIDE;
    if (row2 < NROWS)
        do_row(x, out, row2, lane);
}

extern "C" void kernel_launch(void* const* d_in, const int* in_sizes, int n_in,
                              void* d_out, int out_size)
{
    (void)in_sizes; (void)n_in; (void)out_size;
    const float* x = (const float*)d_in[0];
    float* out = (float*)d_out;
    band_gather_kernel<<<NBLOCKS, TPB>>>(x, out);
}

// round 8
// speedup vs baseline: 1.1144x; 1.0332x over previous
#include <cuda_runtime.h>
#include <cstdint>

// out[b,i,j] = x[b, i, i+j] if i+j < L else 0
// B=4, L=4096, LIMIT=256
#define MAXLEN 4096
#define LIMIT  256
#define BATCH  4

#define NROWS     (BATCH * MAXLEN)     // 16384
#define NSM       148
#define OCC       8
#define NBLOCKS   (NSM * OCC)          // 1184 persistent CTAs (one wave)
#define TPB       256                  // 8 warps; warp handles one row per trip
#define ROWSTRIDE (NBLOCKS * (TPB/32)) // 9472 rows per sweep
#define FULLM     0xFFFFFFFFu

// w1[lane] = src[lane+1], with src[32] supplied by nxt0 (same value all lanes)
__device__ __forceinline__ float4 shift_down1(float4 src, float4 nxt, int lane)
{
    float4 r;
    r.x = __shfl_down_sync(FULLM, src.x, 1);
    r.y = __shfl_down_sync(FULLM, src.y, 1);
    r.z = __shfl_down_sync(FULLM, src.z, 1);
    r.w = __shfl_down_sync(FULLM, src.w, 1);
    if (lane == 31) r = nxt;   // block index lane+1 == 32 -> first block of next group
    return r;
}

__device__ __forceinline__ void do_row(const float* __restrict__ x,
                                       float* __restrict__ out,
                                       int row, int lane)
{
    const int i   = row & (MAXLEN - 1);
    const int a   = i & 3;                   // misalignment, warp-uniform
    const int bc4 = i >> 2;                  // first aligned f4 block in row
    const int lim = MAXLEN - i;              // j < lim is valid
    const float4* __restrict__ xr =
        reinterpret_cast<const float4*>(x) + ((size_t)row << 10);
    float4* __restrict__ orow =
        reinterpret_cast<float4*>(out) + ((size_t)row << 6);

    // Each 16B block loaded exactly ONCE, L2-only (no reuse -> skip L1).
    const float4 A = __ldcg(xr + min(bc4 + lane,      1023));   // blocks 0..31
    const float4 B = __ldcg(xr + min(bc4 + 32 + lane, 1023));   // blocks 32..63
    const float4 C = __ldcg(xr + min(bc4 + 64,        1023));   // block 64 (bcast)

    const float4 B0x = { __shfl_sync(FULLM, B.x, 0), __shfl_sync(FULLM, B.y, 0),
                         __shfl_sync(FULLM, B.z, 0), __shfl_sync(FULLM, B.w, 0) };

    #pragma unroll
    for (int it = 0; it < 2; it++) {
        const int o = lane + it * 32;        // output f4 index (0..63)
        const float4 w0 = it ? B : A;
        const float4 w1 = it ? shift_down1(B, C,   lane)
                             : shift_down1(A, B0x, lane);

        float4 v;                            // funnel shift by a floats
        if      (a == 0) { v.x = w0.x; v.y = w0.y; v.z = w0.z; v.w = w0.w; }
        else if (a == 1) { v.x = w0.y; v.y = w0.z; v.z = w0.w; v.w = w1.x; }
        else if (a == 2) { v.x = w0.z; v.y = w0.w; v.z = w1.x; v.w = w1.y; }
        else             { v.x = w0.w; v.y = w1.x; v.z = w1.y; v.w = w1.z; }

        const int j0 = o << 2;
        if (j0 + 3 >= lim) {                 // rare tail rows only
            if (j0 + 0 >= lim) v.x = 0.0f;
            if (j0 + 1 >= lim) v.y = 0.0f;
            if (j0 + 2 >= lim) v.z = 0.0f;
            if (j0 + 3 >= lim) v.w = 0.0f;
        }
        orow[o] = v;
    }
}

__global__ __launch_bounds__(TPB, OCC)
void band_gather_kernel(const float* __restrict__ x, float* __restrict__ out)
{
    const int lane = threadIdx.x & 31;
    const int warp = blockIdx.x * (TPB / 32) + (threadIdx.x >> 5);

    do_row(x, out, warp, lane);              // rows 0..9471

    const int row2 = warp + ROWSTRIDE;       // rows 9472..16383
    if (row2 < NROWS)
        do_row(x, out, row2, lane);
}

extern "C" void kernel_launch(void* const* d_in, const int* in_sizes, int n_in,
                              void* d_out, int out_size)
{
    (void)in_sizes; (void)n_in; (void)out_size;
    const float* x = (const float*)d_in[0];
    float* out = (float*)d_out;
    band_gather_kernel<<<NBLOCKS, TPB>>>(x, out);
}